// round 12
// baseline (speedup 1.0000x reference)
#include <cuda_runtime.h>
#include <cuda_bf16.h>
#include <math.h>
#include <stdint.h>

#define NN    32768
#define NE    262144
#define BG    32
#define NPG   1024
#define KSEL  820
#define HH    8
#define CC    64
#define HC    512
#define NEG   0.2f

// ------------------------- scratch (static device memory) -------------------------
__device__ float g_xl[(size_t)NN * HC];       // 64 MB
__device__ float g_xr[(size_t)NN * HC];       // 64 MB
__device__ float g_alpha[(size_t)NE * HH];    // 8 MB  (indexed by edge id)
__device__ float g_h[(size_t)NN * HC];        // 64 MB
__device__ float g_score[NN];
__device__ int   g_cnt[NN];
__device__ int   g_off[NN + 1];
__device__ int   g_cur[NN];
__device__ int   g_perm[NE];
__device__ int   g_sel[NN];
__device__ int   g_bsum[32];
__device__ float g_rnorm;
// transposed+split weights: [n=0..1023][k=0..255] bf16
__device__ __align__(16) __nv_bfloat16 g_wthi[1024 * 256];
__device__ __align__(16) __nv_bfloat16 g_wtlo[1024 * 256];
// transposed+split We: [n=0..511][k=0..31] bf16
__device__ __align__(16) __nv_bfloat16 g_wethi[512 * 32];
__device__ __align__(16) __nv_bfloat16 g_wetlo[512 * 32];
// split x: [m][k=256] bf16
__device__ __align__(16) __nv_bfloat16 g_xhi[(size_t)NN * 256];
__device__ __align__(16) __nv_bfloat16 g_xlo[(size_t)NN * 256];

// ------------------------- helpers -------------------------
__device__ __forceinline__ uint32_t smem_u32(const void* p) {
    uint32_t a;
    asm("{ .reg .u64 t; cvta.to.shared.u64 t, %1; cvt.u32.u64 %0, t; }" : "=r"(a) : "l"(p));
    return a;
}
__device__ __forceinline__ uint32_t swz64(uint32_t b) { return b ^ ((b >> 3) & 0x30); }  // SW64

__device__ __forceinline__ void ldm4(uint32_t* r, uint32_t addr) {
    asm volatile("ldmatrix.sync.aligned.m8n8.x4.shared.b16 {%0,%1,%2,%3}, [%4];"
        : "=r"(r[0]), "=r"(r[1]), "=r"(r[2]), "=r"(r[3]) : "r"(addr));
}
__device__ __forceinline__ void mma_bf16(float* c, const uint32_t* a, uint32_t b0, uint32_t b1) {
    asm volatile("mma.sync.aligned.m16n8k16.row.col.f32.bf16.bf16.f32 "
        "{%0,%1,%2,%3},{%4,%5,%6,%7},{%8,%9},{%0,%1,%2,%3};"
        : "+f"(c[0]), "+f"(c[1]), "+f"(c[2]), "+f"(c[3])
        : "r"(a[0]), "r"(a[1]), "r"(a[2]), "r"(a[3]), "r"(b0), "r"(b1));
}
__device__ __forceinline__ void split2(float a, float b, uint32_t& hi, uint32_t& lo) {
    __nv_bfloat162 h = __floats2bfloat162_rn(a, b);
    float2 hf = __bfloat1622float2(h);
    __nv_bfloat162 l = __floats2bfloat162_rn(a - hf.x, b - hf.y);
    hi = *(uint32_t*)&h;
    lo = *(uint32_t*)&l;
}
__device__ __forceinline__ void cpa16(uint32_t s, const void* g) {
    asm volatile("cp.async.cg.shared.global [%0], [%1], 16;" :: "r"(s), "l"(g) : "memory");
}

// ------------------------- merged prep kernel -------------------------
__global__ void __launch_bounds__(256) prep_all(const float* __restrict__ Wl,
                                                const float* __restrict__ Wr,
                                                const float* __restrict__ We,
                                                const float* __restrict__ x) {
    int b = blockIdx.x, tid = threadIdx.x;
    if (b < 1024) {
        int n = b;
        const float* W = (n < 512) ? Wl : Wr;
        int nc = (n < 512) ? n : n - 512;
        float v = W[(size_t)tid * HC + nc];
        __nv_bfloat16 h = __float2bfloat16(v);
        g_wthi[n * 256 + tid] = h;
        g_wtlo[n * 256 + tid] = __float2bfloat16(v - __bfloat162float(h));
    } else if (b < 1088) {
        int idx = (b - 1024) * 256 + tid;
        int n = idx >> 5, k = idx & 31;
        float v = We[(size_t)k * HC + n];
        __nv_bfloat16 h = __float2bfloat16(v);
        g_wethi[n * 32 + k] = h;
        g_wetlo[n * 32 + k] = __float2bfloat16(v - __bfloat162float(h));
    } else {
        size_t i = (size_t)((b - 1088) * 256 + tid) * 4;
        float4 v = *(const float4*)(x + i);
        uint2 hp, lp;
        split2(v.x, v.y, hp.x, lp.x);
        split2(v.z, v.w, hp.y, lp.y);
        *(uint2*)(g_xhi + i) = hp;
        *(uint2*)(g_xlo + i) = lp;
    }
}

// ------------------------- small utility kernels -------------------------
__global__ void k_zero() {
    int i = blockIdx.x * 256 + threadIdx.x;
    if (i < NN) g_cnt[i] = 0;
}

__global__ void k_rnorm(const float* __restrict__ pw) {
    __shared__ float s[512];
    int t = threadIdx.x;
    float v = pw[t];
    s[t] = v * v;
    __syncthreads();
    for (int off = 256; off > 0; off >>= 1) {
        if (t < off) s[t] += s[t + off];
        __syncthreads();
    }
    if (t == 0) g_rnorm = rsqrtf(s[0]);
}

__global__ void k_count(const int* __restrict__ ei) {
    int e = blockIdx.x * 256 + threadIdx.x;
    if (e < NE) atomicAdd(&g_cnt[ei[NE + e]], 1);
}

__global__ void __launch_bounds__(1024) k_scanA() {
    __shared__ int s[1024];
    int b = blockIdx.x, t = threadIdx.x, gi = b * 1024 + t;
    int v = g_cnt[gi];
    s[t] = v;
    __syncthreads();
    for (int off = 1; off < 1024; off <<= 1) {
        int u = (t >= off) ? s[t - off] : 0;
        __syncthreads();
        s[t] += u;
        __syncthreads();
    }
    g_off[gi] = s[t] - v;
    if (t == 1023) g_bsum[b] = s[t];
}

__global__ void k_scanB() {
    int t = threadIdx.x;
    int v = g_bsum[t];
    int x = v;
    for (int off = 1; off < 32; off <<= 1) {
        int u = __shfl_up_sync(0xffffffffu, x, off);
        if (t >= off) x += u;
    }
    g_bsum[t] = x - v;
}

__global__ void __launch_bounds__(1024) k_scanC() {
    int b = blockIdx.x, t = threadIdx.x, gi = b * 1024 + t;
    int o = g_off[gi] + g_bsum[b];
    g_off[gi] = o;
    g_cur[gi] = o;
    if (gi == NN - 1) g_off[NN] = NE;
}

__global__ void k_scatter(const int* __restrict__ ei) {
    int e = blockIdx.x * 256 + threadIdx.x;
    if (e < NE) {
        int d = ei[NE + e];
        int p = atomicAdd(&g_cur[d], 1);
        g_perm[p] = e;
    }
}

// ------------------------- split-bf16 tensor-core GEMM, cp.async pipelined ----------
#define MMA_SMEM 65536

__global__ void __launch_bounds__(256, 2) mma_x(const float* __restrict__ bl,
                                                const float* __restrict__ br) {
    extern __shared__ __align__(128) char sm[];
    uint32_t sb = smem_u32(sm);
    const int tid = threadIdx.x, lane = tid & 31, wid = tid >> 5;
    const int bm = blockIdx.x * 128;
    const int bnb = blockIdx.y;
    const char* pAh = (const char*)g_xhi + (size_t)bm * 512;
    const char* pAl = (const char*)g_xlo + (size_t)bm * 512;
    const char* pBh = (const char*)g_wthi + (size_t)bnb * 128 * 512;
    const char* pBl = (const char*)g_wtlo + (size_t)bnb * 128 * 512;
    const int wm = (wid & 3) * 32, wn = (wid >> 2) * 64;

    float acc[2][8][4];
#pragma unroll
    for (int a = 0; a < 2; a++)
#pragma unroll
        for (int b = 0; b < 8; b++)
#pragma unroll
            for (int c = 0; c < 4; c++) acc[a][b][c] = 0.f;

#pragma unroll
    for (int i = 0; i < 2; i++) {
        int idx = tid + i * 256;
        int r = idx >> 2, ch = idx & 3;
        size_t go = (size_t)r * 512 + ch * 16;
        uint32_t so = sb + swz64(r * 64 + ch * 16);
        cpa16(so,         pAh + go);
        cpa16(so + 8192,  pAl + go);
        cpa16(so + 16384, pBh + go);
        cpa16(so + 24576, pBl + go);
    }
    asm volatile("cp.async.commit_group;" ::: "memory");

#pragma unroll 1
    for (int s = 0; s < 8; s++) {
        if (s < 7) {
            int buf = (s + 1) & 1;
            uint32_t base = sb + buf * 32768;
#pragma unroll
            for (int i = 0; i < 2; i++) {
                int idx = tid + i * 256;
                int r = idx >> 2, ch = idx & 3;
                size_t go = (size_t)r * 512 + (size_t)(s + 1) * 64 + ch * 16;
                uint32_t so = base + swz64(r * 64 + ch * 16);
                cpa16(so,         pAh + go);
                cpa16(so + 8192,  pAl + go);
                cpa16(so + 16384, pBh + go);
                cpa16(so + 24576, pBl + go);
            }
            asm volatile("cp.async.commit_group;" ::: "memory");
            asm volatile("cp.async.wait_group 1;" ::: "memory");
        } else {
            asm volatile("cp.async.wait_group 0;" ::: "memory");
        }
        __syncthreads();

        uint32_t base = sb + (s & 1) * 32768;
#pragma unroll
        for (int kk = 0; kk < 2; kk++) {
            uint32_t ah[2][4], al[2][4];
            const int arow = (lane & 7) + ((lane >> 3) & 1) * 8;
            const uint32_t acol = kk * 32 + (lane >> 4) * 16;
#pragma unroll
            for (int ma = 0; ma < 2; ma++) {
                uint32_t off = swz64((wm + ma * 16 + arow) * 64 + acol);
                ldm4(ah[ma], base + off);
                ldm4(al[ma], base + 8192 + off);
            }
            const int brow = (lane & 7) + (lane >> 4) * 8;
            const uint32_t bcol = kk * 32 + ((lane >> 3) & 1) * 16;
#pragma unroll
            for (int g = 0; g < 2; g++) {
                uint32_t bh[2][4], blo[2][4];
#pragma unroll
                for (int p = 0; p < 2; p++) {
                    uint32_t off = swz64((wn + g * 32 + p * 16 + brow) * 64 + bcol);
                    ldm4(bh[p], base + 16384 + off);
                    ldm4(blo[p], base + 24576 + off);
                }
#pragma unroll
                for (int ma = 0; ma < 2; ma++)
#pragma unroll
                    for (int na = 0; na < 4; na++) {
                        int p = na >> 1, j = na & 1;
                        float* c = acc[ma][g * 4 + na];
                        mma_bf16(c, ah[ma], bh[p][j * 2], bh[p][j * 2 + 1]);
                        mma_bf16(c, ah[ma], blo[p][j * 2], blo[p][j * 2 + 1]);
                        mma_bf16(c, al[ma], bh[p][j * 2], bh[p][j * 2 + 1]);
                    }
            }
        }
        __syncthreads();
    }

#pragma unroll
    for (int ma = 0; ma < 2; ma++)
#pragma unroll
        for (int n = 0; n < 8; n++) {
            int nn = bnb * 128 + wn + n * 8 + (lane & 3) * 2;
            float* C = (nn < 512) ? g_xl : g_xr;
            const float* bias = (nn < 512) ? bl : br;
            int ncol = nn & 511;
            float b0 = bias[ncol], b1 = bias[ncol + 1];
            int r0 = bm + wm + ma * 16 + (lane >> 2);
            float2 v0 = {acc[ma][n][0] + b0, acc[ma][n][1] + b1};
            float2 v1 = {acc[ma][n][2] + b0, acc[ma][n][3] + b1};
            *(float2*)(C + (size_t)r0 * HC + ncol) = v0;
            *(float2*)(C + (size_t)(r0 + 8) * HC + ncol) = v1;
        }
}

// ------------------------- fused eproj MMA GEMM + attention logits -------------------------
// Natural edge order. Tile: 128 edges x 128 ch, K=32. grid (NE/128, 4).
// Epilogue: PER-WARP smem staging of the xl+xr gather. Each warp stages its 8 rows x 64 ch
// slice with coalesced LDG.128 (16 lanes per row) into a private slab (syncwarp only),
// then consumes via LDS. One __syncthreads after the MMA loop frees the smem for reuse.
__global__ void __launch_bounds__(256) k_egemm_alpha(const float* __restrict__ EA,
                                                     const float* __restrict__ att,
                                                     const int* __restrict__ ei) {
    __shared__ __align__(128) char s_all[32768];  // MMA: 4x8192 | later: 8 warp slabs
    __shared__ int s_src[128];
    __shared__ int s_dst[128];
    char* sAh = s_all;
    char* sAl = s_all + 8192;
    char* sBh = s_all + 16384;
    char* sBl = s_all + 24576;
    const int tid = threadIdx.x, lane = tid & 31, wid = tid >> 5;
    const int bm = blockIdx.x * 128;   // edge base
    const int bn = blockIdx.y * 128;   // channel base
    const int wm = (wid & 3) * 32, wn = (wid >> 2) * 64;

    // load + split A (edge_attr)
    {
        int row = tid >> 1, half = tid & 1;
        const float* p = EA + (size_t)(bm + row) * 32 + half * 16;
        uint32_t hi[8], lo[8];
#pragma unroll
        for (int q = 0; q < 4; q++) {
            float4 v = *(const float4*)(p + q * 4);
            split2(v.x, v.y, hi[q * 2], lo[q * 2]);
            split2(v.z, v.w, hi[q * 2 + 1], lo[q * 2 + 1]);
        }
        uint32_t b0 = swz64(row * 64 + half * 32);
        uint32_t b1 = swz64(row * 64 + half * 32 + 16);
        *(uint4*)(sAh + b0) = *(uint4*)(hi);
        *(uint4*)(sAh + b1) = *(uint4*)(hi + 4);
        *(uint4*)(sAl + b0) = *(uint4*)(lo);
        *(uint4*)(sAl + b1) = *(uint4*)(lo + 4);
    }
    // load B (We^T split): 128 rows x 32 bf16
    {
        int nl = tid >> 1, half = tid & 1;
        const char* ph = (const char*)(g_wethi + (size_t)(bn + nl) * 32 + half * 16);
        const char* pl = (const char*)(g_wetlo + (size_t)(bn + nl) * 32 + half * 16);
        uint32_t b0 = swz64(nl * 64 + half * 32);
        uint32_t b1 = swz64(nl * 64 + half * 32 + 16);
        *(uint4*)(sBh + b0) = *(const uint4*)(ph);
        *(uint4*)(sBh + b1) = *(const uint4*)(ph + 16);
        *(uint4*)(sBl + b0) = *(const uint4*)(pl);
        *(uint4*)(sBl + b1) = *(const uint4*)(pl + 16);
    }
    if (tid < 128) s_src[tid] = ei[bm + tid];
    else           s_dst[tid - 128] = ei[NE + bm + tid - 128];
    __syncthreads();

    uint32_t sbAh = smem_u32(sAh), sbAl = smem_u32(sAl);
    uint32_t sbBh = smem_u32(sBh), sbBl = smem_u32(sBl);

    float acc[2][8][4];
#pragma unroll
    for (int a = 0; a < 2; a++)
#pragma unroll
        for (int b = 0; b < 8; b++)
#pragma unroll
            for (int c = 0; c < 4; c++) acc[a][b][c] = 0.f;

#pragma unroll
    for (int kk = 0; kk < 2; kk++) {
        uint32_t ah[2][4], al[2][4];
        const int arow = (lane & 7) + ((lane >> 3) & 1) * 8;
        const uint32_t acol = kk * 32 + (lane >> 4) * 16;
#pragma unroll
        for (int ma = 0; ma < 2; ma++) {
            uint32_t off = swz64((wm + ma * 16 + arow) * 64 + acol);
            ldm4(ah[ma], sbAh + off);
            ldm4(al[ma], sbAl + off);
        }
        const int brow = (lane & 7) + (lane >> 4) * 8;
        const uint32_t bcol = kk * 32 + ((lane >> 3) & 1) * 16;
#pragma unroll
        for (int g = 0; g < 2; g++) {
            uint32_t bh[2][4], blo[2][4];
#pragma unroll
            for (int p = 0; p < 2; p++) {
                uint32_t off = swz64((wn + g * 32 + p * 16 + brow) * 64 + bcol);
                ldm4(bh[p], sbBh + off);
                ldm4(blo[p], sbBl + off);
            }
#pragma unroll
            for (int ma = 0; ma < 2; ma++)
#pragma unroll
                for (int na = 0; na < 4; na++) {
                    int p = na >> 1, j = na & 1;
                    float* c = acc[ma][g * 4 + na];
                    mma_bf16(c, ah[ma], bh[p][j * 2], bh[p][j * 2 + 1]);
                    mma_bf16(c, ah[ma], blo[p][j * 2], blo[p][j * 2 + 1]);
                    mma_bf16(c, al[ma], bh[p][j * 2], bh[p][j * 2 + 1]);
                }
        }
    }

    __syncthreads();  // all warps done reading MMA smem -> safe to reuse as slabs

    // ---- epilogue: per-warp staged coalesced gather + leaky + att dot + reduce ----
    const int qr = lane >> 2, pq = lane & 3;
    const int head = (bn + wn) >> 6;
    float2 attv[8];
#pragma unroll
    for (int n = 0; n < 8; n++)
        attv[n] = *(const float2*)(att + bn + wn + pq * 2 + n * 8);

    float* slab = (float*)s_all + wid * 544;   // 544 floats = 2176 B per warp
    const int rsel = lane >> 4;                 // 0 or 1
    const int colw = (lane & 15) * 4;           // 0..60

#pragma unroll
    for (int ma = 0; ma < 2; ma++) {
#pragma unroll
        for (int half = 0; half < 2; half++) {
            int rbase = wm + ma * 16 + half * 8;
            __syncwarp();
#pragma unroll
            for (int it = 0; it < 4; it++) {
                int rj = it * 2 + rsel;
                int r = rbase + rj;
                const float4 a = *(const float4*)(g_xl + (size_t)s_src[r] * HC + bn + wn + colw);
                const float4 b = *(const float4*)(g_xr + (size_t)s_dst[r] * HC + bn + wn + colw);
                float4 sv;
                sv.x = a.x + b.x; sv.y = a.y + b.y; sv.z = a.z + b.z; sv.w = a.w + b.w;
                *(float4*)(slab + rj * 68 + colw) = sv;
            }
            __syncwarp();
            const float* sp = slab + qr * 68 + pq * 2;
            float s = 0.f;
#pragma unroll
            for (int n = 0; n < 8; n++) {
                float2 lv = *(const float2*)(sp + n * 8);
                float v0 = acc[ma][n][half * 2 + 0] + lv.x;
                float v1 = acc[ma][n][half * 2 + 1] + lv.y;
                v0 = (v0 > 0.f) ? v0 : NEG * v0;
                v1 = (v1 > 0.f) ? v1 : NEG * v1;
                s = fmaf(v0, attv[n].x, s);
                s = fmaf(v1, attv[n].y, s);
            }
            s += __shfl_xor_sync(0xffffffffu, s, 1);
            s += __shfl_xor_sync(0xffffffffu, s, 2);
            if (pq == 0) g_alpha[(size_t)(bm + rbase + qr) * 8 + head] = s;
        }
    }
}

// ------------------------- per-node softmax + aggregation + score -------------------------
__global__ void __launch_bounds__(256) k_node(const int* __restrict__ ei,
                                              const float* __restrict__ bias,
                                              const float* __restrict__ pw) {
    int tid = threadIdx.x;
    int warp = tid >> 5, lane = tid & 31;
    int n = blockIdx.x * 8 + warp;
    int beg = g_off[n], end = g_off[n + 1];

    float m = -INFINITY;
    if (lane < 8) {
        for (int i = beg; i < end; i++) {
            int e = g_perm[i];
            m = fmaxf(m, g_alpha[(size_t)e * 8 + lane]);
        }
    }

    float acc[16];
#pragma unroll
    for (int t = 0; t < 16; t++) acc[t] = 0.f;
    float dsum = 0.f;

    for (int i = beg; i < end; i++) {
        int e = g_perm[i];
        int src = ei[e];
        float w = 0.f;
        if (lane < 8) {
            w = expf(g_alpha[(size_t)e * 8 + lane] - m);
            dsum += w;
        }
        const float* pl = g_xl + (size_t)src * HC;
#pragma unroll
        for (int t = 0; t < 16; t++) {
            int h = t >> 1;
            float wh = __shfl_sync(0xffffffffu, w, h);
            acc[t] = fmaf(wh, pl[lane + 32 * t], acc[t]);
        }
    }

    float invd = (lane < 8 && dsum > 0.f) ? 1.f / dsum : 0.f;

    float sc = 0.f;
#pragma unroll
    for (int t = 0; t < 16; t++) {
        int k = lane + 32 * t;
        int h = t >> 1;
        float id = __shfl_sync(0xffffffffu, invd, h);
        float y = acc[t] * id + bias[k];
        y = fmaxf(y, 0.f);
        g_h[(size_t)n * HC + k] = y;
        sc = fmaf(y, pw[k], sc);
    }
    sc += __shfl_xor_sync(0xffffffffu, sc, 16);
    sc += __shfl_xor_sync(0xffffffffu, sc, 8);
    sc += __shfl_xor_sync(0xffffffffu, sc, 4);
    sc += __shfl_xor_sync(0xffffffffu, sc, 2);
    sc += __shfl_xor_sync(0xffffffffu, sc, 1);
    if (lane == 0) g_score[n] = tanhf(sc * g_rnorm);
}

// ------------------------- top-K selection per graph -------------------------
__global__ void __launch_bounds__(1024) k_topk() {
    __shared__ float s[NPG];
    int b = blockIdx.x, t = threadIdx.x;
    float v = g_score[b * NPG + t];
    s[t] = v;
    __syncthreads();
    int rank = 0;
#pragma unroll 4
    for (int j = 0; j < NPG; j++) {
        float o = s[j];
        rank += (o > v) || (o == v && j < t);
    }
    g_sel[b * NPG + t] = (rank < KSEL) ? 1 : 0;
}

// ------------------------- global max || mean pool over selected rows -------------------------
__global__ void __launch_bounds__(512) k_pool(float* __restrict__ out) {
    __shared__ float sv[NPG];
    __shared__ int sf[NPG];
    int b = blockIdx.x, ch = threadIdx.x;
    for (int j = ch; j < NPG; j += 512) {
        sf[j] = g_sel[b * NPG + j];
        sv[j] = g_score[b * NPG + j];
    }
    __syncthreads();
    float mx = -INFINITY, sm = 0.f;
    for (int j = 0; j < NPG; j++) {
        if (sf[j]) {
            float p = sv[j] * g_h[(size_t)(b * NPG + j) * HC + ch];
            mx = fmaxf(mx, p);
            sm += p;
        }
    }
    out[b * 1024 + ch] = mx;
    out[b * 1024 + 512 + ch] = sm * (1.f / (float)KSEL);
}

// ------------------------- launch -------------------------
extern "C" void kernel_launch(void* const* d_in, const int* in_sizes, int n_in,
                              void* d_out, int out_size) {
    const float* x    = (const float*)d_in[0];
    const float* ea   = (const float*)d_in[1];
    const float* Wl   = (const float*)d_in[2];
    const float* bl   = (const float*)d_in[3];
    const float* Wr   = (const float*)d_in[4];
    const float* br   = (const float*)d_in[5];
    const float* We   = (const float*)d_in[6];
    const float* att  = (const float*)d_in[7];
    const float* bias = (const float*)d_in[8];
    const float* pw   = (const float*)d_in[9];
    const int*   ei   = (const int*)d_in[10];
    float* out = (float*)d_out;

    static bool init_done = false;
    static cudaStream_t s1;
    static cudaEvent_t ev_fork, ev_join;
    if (!init_done) {
        cudaFuncSetAttribute(mma_x, cudaFuncAttributeMaxDynamicSharedMemorySize, MMA_SMEM);
        cudaStreamCreateWithFlags(&s1, cudaStreamNonBlocking);
        cudaEventCreateWithFlags(&ev_fork, cudaEventDisableTiming);
        cudaEventCreateWithFlags(&ev_join, cudaEventDisableTiming);
        init_done = true;
    }

    // fork: CSR-build chain runs on side stream, overlapped with prep/mma/egemm
    cudaEventRecord(ev_fork, 0);
    cudaStreamWaitEvent(s1, ev_fork, 0);

    // main stream (egemm lands in the ncu capture slot)
    prep_all<<<9280, 256>>>(Wl, Wr, We, x);                       // 1
    mma_x<<<dim3(NN / 128, 8), 256, MMA_SMEM>>>(bl, br);          // 2
    k_zero<<<128, 256, 0, s1>>>();                                // 3 (side)
    k_egemm_alpha<<<dim3(NE / 128, 4), 256>>>(ea, att, ei);       // 4

    // side-stream CSR chain
    k_count<<<1024, 256, 0, s1>>>(ei);
    k_scanA<<<32, 1024, 0, s1>>>();
    k_scanB<<<1, 32, 0, s1>>>();
    k_scanC<<<32, 1024, 0, s1>>>();
    k_scatter<<<1024, 256, 0, s1>>>(ei);
    k_rnorm<<<1, 512, 0, s1>>>(pw);
    cudaEventRecord(ev_join, s1);

    // join: k_node needs CSR + alpha + xl
    cudaStreamWaitEvent(0, ev_join, 0);
    k_node<<<NN / 8, 256>>>(ei, bias, pw);
    k_topk<<<BG, 1024>>>();
    k_pool<<<BG, 512>>>(out);
}

// round 13
// speedup vs baseline: 1.3533x; 1.3533x over previous
#include <cuda_runtime.h>
#include <cuda_bf16.h>
#include <math.h>
#include <stdint.h>

#define NN    32768
#define NE    262144
#define BG    32
#define NPG   1024
#define KSEL  820
#define HH    8
#define CC    64
#define HC    512
#define NEG   0.2f

// ------------------------- scratch (static device memory) -------------------------
__device__ float g_xl[(size_t)NN * HC];       // 64 MB
__device__ float g_xr[(size_t)NN * HC];       // 64 MB
__device__ float g_alpha[(size_t)NE * HH];    // 8 MB  (indexed by edge id)
__device__ float g_h[(size_t)NN * HC];        // 64 MB
__device__ float g_score[NN];
__device__ int   g_cnt[NN];
__device__ int   g_off[NN + 1];
__device__ int   g_cur[NN];
__device__ int   g_perm[NE];
__device__ int   g_sel[NN];
__device__ int   g_bsum[32];
__device__ float g_rnorm;
// transposed+split weights: [n=0..1023][k=0..255] bf16
__device__ __align__(16) __nv_bfloat16 g_wthi[1024 * 256];
__device__ __align__(16) __nv_bfloat16 g_wtlo[1024 * 256];
// transposed+split We: [n=0..511][k=0..31] bf16
__device__ __align__(16) __nv_bfloat16 g_wethi[512 * 32];
__device__ __align__(16) __nv_bfloat16 g_wetlo[512 * 32];
// split x: [m][k=256] bf16
__device__ __align__(16) __nv_bfloat16 g_xhi[(size_t)NN * 256];
__device__ __align__(16) __nv_bfloat16 g_xlo[(size_t)NN * 256];

// ------------------------- helpers -------------------------
__device__ __forceinline__ uint32_t smem_u32(const void* p) {
    uint32_t a;
    asm("{ .reg .u64 t; cvta.to.shared.u64 t, %1; cvt.u32.u64 %0, t; }" : "=r"(a) : "l"(p));
    return a;
}
__device__ __forceinline__ uint32_t swz64(uint32_t b) { return b ^ ((b >> 3) & 0x30); }  // SW64

__device__ __forceinline__ void ldm4(uint32_t* r, uint32_t addr) {
    asm volatile("ldmatrix.sync.aligned.m8n8.x4.shared.b16 {%0,%1,%2,%3}, [%4];"
        : "=r"(r[0]), "=r"(r[1]), "=r"(r[2]), "=r"(r[3]) : "r"(addr));
}
__device__ __forceinline__ void mma_bf16(float* c, const uint32_t* a, uint32_t b0, uint32_t b1) {
    asm volatile("mma.sync.aligned.m16n8k16.row.col.f32.bf16.bf16.f32 "
        "{%0,%1,%2,%3},{%4,%5,%6,%7},{%8,%9},{%0,%1,%2,%3};"
        : "+f"(c[0]), "+f"(c[1]), "+f"(c[2]), "+f"(c[3])
        : "r"(a[0]), "r"(a[1]), "r"(a[2]), "r"(a[3]), "r"(b0), "r"(b1));
}
__device__ __forceinline__ void split2(float a, float b, uint32_t& hi, uint32_t& lo) {
    __nv_bfloat162 h = __floats2bfloat162_rn(a, b);
    float2 hf = __bfloat1622float2(h);
    __nv_bfloat162 l = __floats2bfloat162_rn(a - hf.x, b - hf.y);
    hi = *(uint32_t*)&h;
    lo = *(uint32_t*)&l;
}
__device__ __forceinline__ void cpa16(uint32_t s, const void* g) {
    asm volatile("cp.async.cg.shared.global [%0], [%1], 16;" :: "r"(s), "l"(g) : "memory");
}

// ------------------------- merged prep kernel -------------------------
__global__ void __launch_bounds__(256) prep_all(const float* __restrict__ Wl,
                                                const float* __restrict__ Wr,
                                                const float* __restrict__ We,
                                                const float* __restrict__ x) {
    int b = blockIdx.x, tid = threadIdx.x;
    if (b < 1024) {
        int n = b;
        const float* W = (n < 512) ? Wl : Wr;
        int nc = (n < 512) ? n : n - 512;
        float v = W[(size_t)tid * HC + nc];
        __nv_bfloat16 h = __float2bfloat16(v);
        g_wthi[n * 256 + tid] = h;
        g_wtlo[n * 256 + tid] = __float2bfloat16(v - __bfloat162float(h));
    } else if (b < 1088) {
        int idx = (b - 1024) * 256 + tid;
        int n = idx >> 5, k = idx & 31;
        float v = We[(size_t)k * HC + n];
        __nv_bfloat16 h = __float2bfloat16(v);
        g_wethi[n * 32 + k] = h;
        g_wetlo[n * 32 + k] = __float2bfloat16(v - __bfloat162float(h));
    } else {
        size_t i = (size_t)((b - 1088) * 256 + tid) * 4;
        float4 v = *(const float4*)(x + i);
        uint2 hp, lp;
        split2(v.x, v.y, hp.x, lp.x);
        split2(v.z, v.w, hp.y, lp.y);
        *(uint2*)(g_xhi + i) = hp;
        *(uint2*)(g_xlo + i) = lp;
    }
}

// ------------------------- small utility kernels -------------------------
__global__ void k_zero() {
    int i = blockIdx.x * 256 + threadIdx.x;
    if (i < NN) g_cnt[i] = 0;
}

__global__ void k_rnorm(const float* __restrict__ pw) {
    __shared__ float s[512];
    int t = threadIdx.x;
    float v = pw[t];
    s[t] = v * v;
    __syncthreads();
    for (int off = 256; off > 0; off >>= 1) {
        if (t < off) s[t] += s[t + off];
        __syncthreads();
    }
    if (t == 0) g_rnorm = rsqrtf(s[0]);
}

__global__ void k_count(const int* __restrict__ ei) {
    int e = blockIdx.x * 256 + threadIdx.x;
    if (e < NE) atomicAdd(&g_cnt[ei[NE + e]], 1);
}

__global__ void __launch_bounds__(1024) k_scanA() {
    __shared__ int s[1024];
    int b = blockIdx.x, t = threadIdx.x, gi = b * 1024 + t;
    int v = g_cnt[gi];
    s[t] = v;
    __syncthreads();
    for (int off = 1; off < 1024; off <<= 1) {
        int u = (t >= off) ? s[t - off] : 0;
        __syncthreads();
        s[t] += u;
        __syncthreads();
    }
    g_off[gi] = s[t] - v;
    if (t == 1023) g_bsum[b] = s[t];
}

__global__ void k_scanB() {
    int t = threadIdx.x;
    int v = g_bsum[t];
    int x = v;
    for (int off = 1; off < 32; off <<= 1) {
        int u = __shfl_up_sync(0xffffffffu, x, off);
        if (t >= off) x += u;
    }
    g_bsum[t] = x - v;
}

__global__ void __launch_bounds__(1024) k_scanC() {
    int b = blockIdx.x, t = threadIdx.x, gi = b * 1024 + t;
    int o = g_off[gi] + g_bsum[b];
    g_off[gi] = o;
    g_cur[gi] = o;
    if (gi == NN - 1) g_off[NN] = NE;
}

__global__ void k_scatter(const int* __restrict__ ei) {
    int e = blockIdx.x * 256 + threadIdx.x;
    if (e < NE) {
        int d = ei[NE + e];
        int p = atomicAdd(&g_cur[d], 1);
        g_perm[p] = e;
    }
}

// ------------------------- split-bf16 tensor-core GEMM, cp.async pipelined ----------
#define MMA_SMEM 65536

__global__ void __launch_bounds__(256, 2) mma_x(const float* __restrict__ bl,
                                                const float* __restrict__ br) {
    extern __shared__ __align__(128) char sm[];
    uint32_t sb = smem_u32(sm);
    const int tid = threadIdx.x, lane = tid & 31, wid = tid >> 5;
    const int bm = blockIdx.x * 128;
    const int bnb = blockIdx.y;
    const char* pAh = (const char*)g_xhi + (size_t)bm * 512;
    const char* pAl = (const char*)g_xlo + (size_t)bm * 512;
    const char* pBh = (const char*)g_wthi + (size_t)bnb * 128 * 512;
    const char* pBl = (const char*)g_wtlo + (size_t)bnb * 128 * 512;
    const int wm = (wid & 3) * 32, wn = (wid >> 2) * 64;

    float acc[2][8][4];
#pragma unroll
    for (int a = 0; a < 2; a++)
#pragma unroll
        for (int b = 0; b < 8; b++)
#pragma unroll
            for (int c = 0; c < 4; c++) acc[a][b][c] = 0.f;

#pragma unroll
    for (int i = 0; i < 2; i++) {
        int idx = tid + i * 256;
        int r = idx >> 2, ch = idx & 3;
        size_t go = (size_t)r * 512 + ch * 16;
        uint32_t so = sb + swz64(r * 64 + ch * 16);
        cpa16(so,         pAh + go);
        cpa16(so + 8192,  pAl + go);
        cpa16(so + 16384, pBh + go);
        cpa16(so + 24576, pBl + go);
    }
    asm volatile("cp.async.commit_group;" ::: "memory");

#pragma unroll 1
    for (int s = 0; s < 8; s++) {
        if (s < 7) {
            int buf = (s + 1) & 1;
            uint32_t base = sb + buf * 32768;
#pragma unroll
            for (int i = 0; i < 2; i++) {
                int idx = tid + i * 256;
                int r = idx >> 2, ch = idx & 3;
                size_t go = (size_t)r * 512 + (size_t)(s + 1) * 64 + ch * 16;
                uint32_t so = base + swz64(r * 64 + ch * 16);
                cpa16(so,         pAh + go);
                cpa16(so + 8192,  pAl + go);
                cpa16(so + 16384, pBh + go);
                cpa16(so + 24576, pBl + go);
            }
            asm volatile("cp.async.commit_group;" ::: "memory");
            asm volatile("cp.async.wait_group 1;" ::: "memory");
        } else {
            asm volatile("cp.async.wait_group 0;" ::: "memory");
        }
        __syncthreads();

        uint32_t base = sb + (s & 1) * 32768;
#pragma unroll
        for (int kk = 0; kk < 2; kk++) {
            uint32_t ah[2][4], al[2][4];
            const int arow = (lane & 7) + ((lane >> 3) & 1) * 8;
            const uint32_t acol = kk * 32 + (lane >> 4) * 16;
#pragma unroll
            for (int ma = 0; ma < 2; ma++) {
                uint32_t off = swz64((wm + ma * 16 + arow) * 64 + acol);
                ldm4(ah[ma], base + off);
                ldm4(al[ma], base + 8192 + off);
            }
            const int brow = (lane & 7) + (lane >> 4) * 8;
            const uint32_t bcol = kk * 32 + ((lane >> 3) & 1) * 16;
#pragma unroll
            for (int g = 0; g < 2; g++) {
                uint32_t bh[2][4], blo[2][4];
#pragma unroll
                for (int p = 0; p < 2; p++) {
                    uint32_t off = swz64((wn + g * 32 + p * 16 + brow) * 64 + bcol);
                    ldm4(bh[p], base + 16384 + off);
                    ldm4(blo[p], base + 24576 + off);
                }
#pragma unroll
                for (int ma = 0; ma < 2; ma++)
#pragma unroll
                    for (int na = 0; na < 4; na++) {
                        int p = na >> 1, j = na & 1;
                        float* c = acc[ma][g * 4 + na];
                        mma_bf16(c, ah[ma], bh[p][j * 2], bh[p][j * 2 + 1]);
                        mma_bf16(c, ah[ma], blo[p][j * 2], blo[p][j * 2 + 1]);
                        mma_bf16(c, al[ma], bh[p][j * 2], bh[p][j * 2 + 1]);
                    }
            }
        }
        __syncthreads();
    }

#pragma unroll
    for (int ma = 0; ma < 2; ma++)
#pragma unroll
        for (int n = 0; n < 8; n++) {
            int nn = bnb * 128 + wn + n * 8 + (lane & 3) * 2;
            float* C = (nn < 512) ? g_xl : g_xr;
            const float* bias = (nn < 512) ? bl : br;
            int ncol = nn & 511;
            float b0 = bias[ncol], b1 = bias[ncol + 1];
            int r0 = bm + wm + ma * 16 + (lane >> 2);
            float2 v0 = {acc[ma][n][0] + b0, acc[ma][n][1] + b1};
            float2 v1 = {acc[ma][n][2] + b0, acc[ma][n][3] + b1};
            *(float2*)(C + (size_t)r0 * HC + ncol) = v0;
            *(float2*)(C + (size_t)(r0 + 8) * HC + ncol) = v1;
        }
}

// ------------------------- fused eproj MMA GEMM + attention logits -------------------------
// Natural edge order, DIRECT gather epilogue (proven optimum, 128 regs / 2 CTAs/SM).
// Tile: 128 edges x 128 ch, K=32. grid (NE/128, 4).
__global__ void __launch_bounds__(256) k_egemm_alpha(const float* __restrict__ EA,
                                                     const float* __restrict__ att,
                                                     const int* __restrict__ ei) {
    __shared__ __align__(128) char sAh[8192];
    __shared__ __align__(128) char sAl[8192];
    __shared__ __align__(128) char sBh[8192];
    __shared__ __align__(128) char sBl[8192];
    __shared__ int s_src[128];
    __shared__ int s_dst[128];
    const int tid = threadIdx.x, lane = tid & 31, wid = tid >> 5;
    const int bm = blockIdx.x * 128;   // edge base
    const int bn = blockIdx.y * 128;   // channel base
    const int wm = (wid & 3) * 32, wn = (wid >> 2) * 64;

    // load + split A (edge_attr)
    {
        int row = tid >> 1, half = tid & 1;
        const float* p = EA + (size_t)(bm + row) * 32 + half * 16;
        uint32_t hi[8], lo[8];
#pragma unroll
        for (int q = 0; q < 4; q++) {
            float4 v = *(const float4*)(p + q * 4);
            split2(v.x, v.y, hi[q * 2], lo[q * 2]);
            split2(v.z, v.w, hi[q * 2 + 1], lo[q * 2 + 1]);
        }
        uint32_t b0 = swz64(row * 64 + half * 32);
        uint32_t b1 = swz64(row * 64 + half * 32 + 16);
        *(uint4*)(sAh + b0) = *(uint4*)(hi);
        *(uint4*)(sAh + b1) = *(uint4*)(hi + 4);
        *(uint4*)(sAl + b0) = *(uint4*)(lo);
        *(uint4*)(sAl + b1) = *(uint4*)(lo + 4);
    }
    // load B (We^T split): 128 rows x 32 bf16
    {
        int nl = tid >> 1, half = tid & 1;
        const char* ph = (const char*)(g_wethi + (size_t)(bn + nl) * 32 + half * 16);
        const char* pl = (const char*)(g_wetlo + (size_t)(bn + nl) * 32 + half * 16);
        uint32_t b0 = swz64(nl * 64 + half * 32);
        uint32_t b1 = swz64(nl * 64 + half * 32 + 16);
        *(uint4*)(sBh + b0) = *(const uint4*)(ph);
        *(uint4*)(sBh + b1) = *(const uint4*)(ph + 16);
        *(uint4*)(sBl + b0) = *(const uint4*)(pl);
        *(uint4*)(sBl + b1) = *(const uint4*)(pl + 16);
    }
    if (tid < 128) s_src[tid] = ei[bm + tid];
    else           s_dst[tid - 128] = ei[NE + bm + tid - 128];
    __syncthreads();

    uint32_t sbAh = smem_u32(sAh), sbAl = smem_u32(sAl);
    uint32_t sbBh = smem_u32(sBh), sbBl = smem_u32(sBl);

    float acc[2][8][4];
#pragma unroll
    for (int a = 0; a < 2; a++)
#pragma unroll
        for (int b = 0; b < 8; b++)
#pragma unroll
            for (int c = 0; c < 4; c++) acc[a][b][c] = 0.f;

#pragma unroll
    for (int kk = 0; kk < 2; kk++) {
        uint32_t ah[2][4], al[2][4];
        const int arow = (lane & 7) + ((lane >> 3) & 1) * 8;
        const uint32_t acol = kk * 32 + (lane >> 4) * 16;
#pragma unroll
        for (int ma = 0; ma < 2; ma++) {
            uint32_t off = swz64((wm + ma * 16 + arow) * 64 + acol);
            ldm4(ah[ma], sbAh + off);
            ldm4(al[ma], sbAl + off);
        }
        const int brow = (lane & 7) + (lane >> 4) * 8;
        const uint32_t bcol = kk * 32 + ((lane >> 3) & 1) * 16;
#pragma unroll
        for (int g = 0; g < 2; g++) {
            uint32_t bh[2][4], blo[2][4];
#pragma unroll
            for (int p = 0; p < 2; p++) {
                uint32_t off = swz64((wn + g * 32 + p * 16 + brow) * 64 + bcol);
                ldm4(bh[p], sbBh + off);
                ldm4(blo[p], sbBl + off);
            }
#pragma unroll
            for (int ma = 0; ma < 2; ma++)
#pragma unroll
                for (int na = 0; na < 4; na++) {
                    int p = na >> 1, j = na & 1;
                    float* c = acc[ma][g * 4 + na];
                    mma_bf16(c, ah[ma], bh[p][j * 2], bh[p][j * 2 + 1]);
                    mma_bf16(c, ah[ma], blo[p][j * 2], blo[p][j * 2 + 1]);
                    mma_bf16(c, al[ma], bh[p][j * 2], bh[p][j * 2 + 1]);
                }
        }
    }

    // epilogue: direct gather xl/xr, leaky, dot att, reduce to alpha[e, head]
    const int c0 = wn + (lane & 3) * 2;
    const int head = (bn + wn) >> 6;
    float2 attv[8];
#pragma unroll
    for (int n = 0; n < 8; n++) attv[n] = *(const float2*)(att + bn + c0 + n * 8);

#pragma unroll
    for (int ma = 0; ma < 2; ma++) {
#pragma unroll
        for (int half = 0; half < 2; half++) {
            int r = wm + ma * 16 + (lane >> 2) + half * 8;
            const float* pl = g_xl + (size_t)s_src[r] * HC + bn + c0;
            const float* pr = g_xr + (size_t)s_dst[r] * HC + bn + c0;
            float s = 0.f;
#pragma unroll
            for (int n = 0; n < 8; n++) {
                float2 l = *(const float2*)(pl + n * 8);
                float2 rr = *(const float2*)(pr + n * 8);
                float v0 = acc[ma][n][half * 2 + 0] + l.x + rr.x;
                float v1 = acc[ma][n][half * 2 + 1] + l.y + rr.y;
                v0 = (v0 > 0.f) ? v0 : NEG * v0;
                v1 = (v1 > 0.f) ? v1 : NEG * v1;
                s = fmaf(v0, attv[n].x, s);
                s = fmaf(v1, attv[n].y, s);
            }
            s += __shfl_xor_sync(0xffffffffu, s, 1);
            s += __shfl_xor_sync(0xffffffffu, s, 2);
            if ((lane & 3) == 0) g_alpha[(size_t)(bm + r) * 8 + head] = s;
        }
    }
}

// ------------------------- per-node softmax + aggregation + score (float4) ------------
// Thread `lane` owns channels k = t*128 + lane*4 (t=0..3); head(t) = 2t + (lane>>4).
// 4x LDG.128 per edge instead of 16x LDG.32.
__global__ void __launch_bounds__(256) k_node(const int* __restrict__ ei,
                                              const float* __restrict__ bias,
                                              const float* __restrict__ pw) {
    int tid = threadIdx.x;
    int warp = tid >> 5, lane = tid & 31;
    int n = blockIdx.x * 8 + warp;
    int beg = g_off[n], end = g_off[n + 1];
    const int hsel = lane >> 4;

    float m = -INFINITY;
    if (lane < 8) {
        for (int i = beg; i < end; i++) {
            int e = g_perm[i];
            m = fmaxf(m, g_alpha[(size_t)e * 8 + lane]);
        }
    }

    float4 acc4[4];
#pragma unroll
    for (int t = 0; t < 4; t++) acc4[t] = make_float4(0.f, 0.f, 0.f, 0.f);
    float dsum = 0.f;

    for (int i = beg; i < end; i++) {
        int e = g_perm[i];
        int src = ei[e];
        float w = 0.f;
        if (lane < 8) {
            w = expf(g_alpha[(size_t)e * 8 + lane] - m);
            dsum += w;
        }
        const float4* pl = (const float4*)(g_xl + (size_t)src * HC) + lane;
#pragma unroll
        for (int t = 0; t < 4; t++) {
            float wh = __shfl_sync(0xffffffffu, w, 2 * t + hsel);
            float4 xv = pl[t * 32];
            acc4[t].x = fmaf(wh, xv.x, acc4[t].x);
            acc4[t].y = fmaf(wh, xv.y, acc4[t].y);
            acc4[t].z = fmaf(wh, xv.z, acc4[t].z);
            acc4[t].w = fmaf(wh, xv.w, acc4[t].w);
        }
    }

    float invd = (lane < 8 && dsum > 0.f) ? 1.f / dsum : 0.f;

    float sc = 0.f;
#pragma unroll
    for (int t = 0; t < 4; t++) {
        int k = t * 128 + lane * 4;
        float id = __shfl_sync(0xffffffffu, invd, 2 * t + hsel);
        float4 b4 = *(const float4*)(bias + k);
        float4 p4 = *(const float4*)(pw + k);
        float4 y;
        y.x = fmaxf(acc4[t].x * id + b4.x, 0.f);
        y.y = fmaxf(acc4[t].y * id + b4.y, 0.f);
        y.z = fmaxf(acc4[t].z * id + b4.z, 0.f);
        y.w = fmaxf(acc4[t].w * id + b4.w, 0.f);
        *(float4*)(g_h + (size_t)n * HC + k) = y;
        sc = fmaf(y.x, p4.x, sc);
        sc = fmaf(y.y, p4.y, sc);
        sc = fmaf(y.z, p4.z, sc);
        sc = fmaf(y.w, p4.w, sc);
    }
    sc += __shfl_xor_sync(0xffffffffu, sc, 16);
    sc += __shfl_xor_sync(0xffffffffu, sc, 8);
    sc += __shfl_xor_sync(0xffffffffu, sc, 4);
    sc += __shfl_xor_sync(0xffffffffu, sc, 2);
    sc += __shfl_xor_sync(0xffffffffu, sc, 1);
    if (lane == 0) g_score[n] = tanhf(sc * g_rnorm);
}

// ------------------------- top-K selection per graph -------------------------
__global__ void __launch_bounds__(1024) k_topk() {
    __shared__ float s[NPG];
    int b = blockIdx.x, t = threadIdx.x;
    float v = g_score[b * NPG + t];
    s[t] = v;
    __syncthreads();
    int rank = 0;
#pragma unroll 4
    for (int j = 0; j < NPG; j++) {
        float o = s[j];
        rank += (o > v) || (o == v && j < t);
    }
    g_sel[b * NPG + t] = (rank < KSEL) ? 1 : 0;
}

// ------------------------- global max || mean pool over selected rows -------------------------
__global__ void __launch_bounds__(512) k_pool(float* __restrict__ out) {
    __shared__ float sv[NPG];
    __shared__ int sf[NPG];
    int b = blockIdx.x, ch = threadIdx.x;
    for (int j = ch; j < NPG; j += 512) {
        sf[j] = g_sel[b * NPG + j];
        sv[j] = g_score[b * NPG + j];
    }
    __syncthreads();
    float mx = -INFINITY, sm = 0.f;
    for (int j = 0; j < NPG; j++) {
        if (sf[j]) {
            float p = sv[j] * g_h[(size_t)(b * NPG + j) * HC + ch];
            mx = fmaxf(mx, p);
            sm += p;
        }
    }
    out[b * 1024 + ch] = mx;
    out[b * 1024 + 512 + ch] = sm * (1.f / (float)KSEL);
}

// ------------------------- launch -------------------------
extern "C" void kernel_launch(void* const* d_in, const int* in_sizes, int n_in,
                              void* d_out, int out_size) {
    const float* x    = (const float*)d_in[0];
    const float* ea   = (const float*)d_in[1];
    const float* Wl   = (const float*)d_in[2];
    const float* bl   = (const float*)d_in[3];
    const float* Wr   = (const float*)d_in[4];
    const float* br   = (const float*)d_in[5];
    const float* We   = (const float*)d_in[6];
    const float* att  = (const float*)d_in[7];
    const float* bias = (const float*)d_in[8];
    const float* pw   = (const float*)d_in[9];
    const int*   ei   = (const int*)d_in[10];
    float* out = (float*)d_out;

    static bool init_done = false;
    static cudaStream_t s1;
    static cudaEvent_t ev_fork, ev_join;
    if (!init_done) {
        cudaFuncSetAttribute(mma_x, cudaFuncAttributeMaxDynamicSharedMemorySize, MMA_SMEM);
        cudaStreamCreateWithFlags(&s1, cudaStreamNonBlocking);
        cudaEventCreateWithFlags(&ev_fork, cudaEventDisableTiming);
        cudaEventCreateWithFlags(&ev_join, cudaEventDisableTiming);
        init_done = true;
    }

    // fork: CSR-build chain runs on side stream, overlapped with prep/mma/egemm
    cudaEventRecord(ev_fork, 0);
    cudaStreamWaitEvent(s1, ev_fork, 0);

    // main stream (egemm lands in the ncu capture slot)
    prep_all<<<9280, 256>>>(Wl, Wr, We, x);                       // 1
    mma_x<<<dim3(NN / 128, 8), 256, MMA_SMEM>>>(bl, br);          // 2
    k_zero<<<128, 256, 0, s1>>>();                                // 3 (side)
    k_egemm_alpha<<<dim3(NE / 128, 4), 256>>>(ea, att, ei);       // 4

    // side-stream CSR chain
    k_count<<<1024, 256, 0, s1>>>(ei);
    k_scanA<<<32, 1024, 0, s1>>>();
    k_scanB<<<1, 32, 0, s1>>>();
    k_scanC<<<32, 1024, 0, s1>>>();
    k_scatter<<<1024, 256, 0, s1>>>(ei);
    k_rnorm<<<1, 512, 0, s1>>>(pw);
    cudaEventRecord(ev_join, s1);

    // join: k_node needs CSR + alpha + xl
    cudaStreamWaitEvent(0, ev_join, 0);
    k_node<<<NN / 8, 256>>>(ei, bias, pw);
    k_topk<<<BG, 1024>>>();
    k_pool<<<BG, 512>>>(out);
}